// round 7
// baseline (speedup 1.0000x reference)
#include <cuda_runtime.h>

// Fixed shapes: B=8, H=8, S=16384, Dv=64, d_k=1
#define BH      64
#define SEQ     16384
#define DV      64
#define NSPLIT  16
#define CHUNK   (SEQ / NSPLIT)     // 1024 rows per reduce item
#define PSTRIDE 68                 // 64 ktv + ksq + qsq, float4-aligned
#define BROWS   256                // rows per broadcast CTA
#define NB_PER_BH (SEQ / BROWS)    // 64 broadcast CTAs per bh
#define N_RED   (BH * NSPLIT)      // 1024 reduce CTAs
#define N_BRD   (BH * NB_PER_BH)   // 4096 broadcast CTAs

__device__ float g_part[BH * NSPLIT * PSTRIDE];
__device__ int   g_done[BH];   // reduce splits finished per bh (self-resetting)
__device__ int   g_bfin[BH];   // broadcast CTAs finished per bh (self-resetting)

struct Smem {
    float  sK[CHUNK];             // reduce: K chunk / broadcast: sQ uses [0,256)
    float4 s_acc[8][16];
    float  s_ksq[8];
    float  s_qsq[8];
    float  s_coef[DV];
    float  s_scale;
};

// ---------------------------------------------------------------------------
// Reduce one (bh, split): proven R2/R3 loop (2 loads/body, unroll 4, MLP 8).
// ---------------------------------------------------------------------------
__device__ __forceinline__ void do_reduce(
    const float* __restrict__ Q, const float* __restrict__ K,
    const float* __restrict__ V, int bh, int split, Smem& sm, int t)
{
    const int colg = t & 15;
    const int rowg = t >> 4;

    const float4* __restrict__ Vp4 =
        reinterpret_cast<const float4*>(V + (size_t)bh * SEQ * DV + (size_t)(split * CHUNK) * DV);
    const float4* __restrict__ Kp4 =
        reinterpret_cast<const float4*>(K + bh * SEQ + split * CHUNK);
    const float4* __restrict__ Qp4 =
        reinterpret_cast<const float4*>(Q + bh * SEQ + split * CHUNK);

    float4 kv = Kp4[t];
    reinterpret_cast<float4*>(sm.sK)[t] = kv;
    float ksq = kv.x * kv.x + kv.y * kv.y + kv.z * kv.z + kv.w * kv.w;
    float4 qv = Qp4[t];
    float qsq = qv.x * qv.x + qv.y * qv.y + qv.z * qv.z + qv.w * qv.w;
    __syncthreads();

    float4 a0 = make_float4(0.f, 0.f, 0.f, 0.f);
    float4 a1 = make_float4(0.f, 0.f, 0.f, 0.f);

    #pragma unroll 4
    for (int r = rowg; r < CHUNK; r += 32) {
        float  k0 = sm.sK[r];
        float4 v0 = __ldcs(&Vp4[(size_t)r * 16 + colg]);
        float  k1 = sm.sK[r + 16];
        float4 v1 = __ldcs(&Vp4[(size_t)(r + 16) * 16 + colg]);
        a0.x += k0 * v0.x;  a0.y += k0 * v0.y;  a0.z += k0 * v0.z;  a0.w += k0 * v0.w;
        a1.x += k1 * v1.x;  a1.y += k1 * v1.y;  a1.z += k1 * v1.z;  a1.w += k1 * v1.w;
    }
    a0.x += a1.x; a0.y += a1.y; a0.z += a1.z; a0.w += a1.w;

    a0.x += __shfl_xor_sync(0xFFFFFFFFu, a0.x, 16);
    a0.y += __shfl_xor_sync(0xFFFFFFFFu, a0.y, 16);
    a0.z += __shfl_xor_sync(0xFFFFFFFFu, a0.z, 16);
    a0.w += __shfl_xor_sync(0xFFFFFFFFu, a0.w, 16);

    #pragma unroll
    for (int m = 16; m >= 1; m >>= 1) {
        ksq += __shfl_xor_sync(0xFFFFFFFFu, ksq, m);
        qsq += __shfl_xor_sync(0xFFFFFFFFu, qsq, m);
    }

    const int warp = t >> 5;
    const int lane = t & 31;
    if (lane < 16) sm.s_acc[warp][lane] = a0;
    if (lane == 0) { sm.s_ksq[warp] = ksq; sm.s_qsq[warp] = qsq; }
    __syncthreads();

    float* __restrict__ outp = g_part + (size_t)(bh * NSPLIT + split) * PSTRIDE;
    if (t < 16) {
        float4 a = sm.s_acc[0][t];
        #pragma unroll
        for (int w = 1; w < 8; ++w) {
            float4 b = sm.s_acc[w][t];
            a.x += b.x; a.y += b.y; a.z += b.z; a.w += b.w;
        }
        reinterpret_cast<float4*>(outp)[t] = a;
    } else if (t == 16) {
        float a = 0.f, b = 0.f;
        #pragma unroll
        for (int w = 0; w < 8; ++w) { a += sm.s_ksq[w]; b += sm.s_qsq[w]; }
        outp[64] = a;
        outp[65] = b;
    }

    __threadfence();
    __syncthreads();
    if (t == 0) atomicAdd(&g_done[bh], 1);
}

// ---------------------------------------------------------------------------
// Broadcast one 256-row chunk of bh: wait for its 16 splits, combine coef,
// stream stores. Last finisher per bh resets the counters for graph replay.
// ---------------------------------------------------------------------------
__device__ __forceinline__ void do_broadcast(
    const float* __restrict__ Q, float* __restrict__ out,
    int bh, int chunk, Smem& sm, int t)
{
    if (t == 0) {
        while (((volatile int*)g_done)[bh] < NSPLIT) __nanosleep(128);
        __threadfence();
    }
    const size_t row0 = (size_t)bh * SEQ + (size_t)chunk * BROWS;
    __syncthreads();

    sm.sK[t] = Q[row0 + t];   // stage Q slice

    const float* __restrict__ base = g_part + (size_t)bh * NSPLIT * PSTRIDE;
    if (t < DV) {
        float ktv = 0.f;
        #pragma unroll
        for (int s = 0; s < NSPLIT; ++s) ktv += base[(size_t)s * PSTRIDE + t];
        sm.s_coef[t] = ktv;
    } else if (t == DV) {
        float ksq = 0.f, qsq = 0.f;
        #pragma unroll
        for (int s = 0; s < NSPLIT; ++s) {
            ksq += base[(size_t)s * PSTRIDE + 64];
            qsq += base[(size_t)s * PSTRIDE + 65];
        }
        sm.s_scale = 1.0f / (sqrtf(ksq) * sqrtf(qsq));
    }
    __syncthreads();

    const int rg = t >> 4;
    const int cg = t & 15;
    const float scale = sm.s_scale;
    float4 c = reinterpret_cast<const float4*>(sm.s_coef)[cg];
    c.x *= scale; c.y *= scale; c.z *= scale; c.w *= scale;

    #pragma unroll
    for (int ri = 0; ri < BROWS / 16; ++ri) {
        const int    lr  = ri * 16 + rg;
        const size_t row = row0 + lr;
        const float  q   = sm.sK[lr];
        float4 o;
        o.x = q * c.x;
        o.y = q * c.y;
        o.z = q * c.z;
        o.w = q * c.w;
        __stcs(reinterpret_cast<float4*>(out) + row * 16 + cg, o);
    }

    __syncthreads();
    if (t == 0) {
        int v = atomicAdd(&g_bfin[bh], 1);
        if (v == NB_PER_BH - 1) {     // last broadcast CTA of this bh
            g_done[bh] = 0;
            g_bfin[bh] = 0;
        }
    }
}

// ---------------------------------------------------------------------------
// One launch: bids [0, 1024) = reduce items; bids [1024, 5120) = broadcast
// items ordered by bh. HW dispatches low bids first, so the chip fills with
// reduce work; broadcast CTAs flow in as reduce retires (waits only on
// strictly-lower bids -> deadlock-free).
// ---------------------------------------------------------------------------
__global__ __launch_bounds__(256) void fused_kernel(
    const float* __restrict__ Q,
    const float* __restrict__ K,
    const float* __restrict__ V,
    float* __restrict__ out)
{
    __shared__ Smem sm;
    const int bid = blockIdx.x;
    const int t   = threadIdx.x;

    if (bid < N_RED) {
        do_reduce(Q, K, V, bid / NSPLIT, bid % NSPLIT, sm, t);
    } else {
        const int j = bid - N_RED;
        do_broadcast(Q, out, j / NB_PER_BH, j % NB_PER_BH, sm, t);
    }
}

// ---------------------------------------------------------------------------
extern "C" void kernel_launch(void* const* d_in, const int* in_sizes, int n_in,
                              void* d_out, int out_size)
{
    const float* Q = (const float*)d_in[0];
    const float* K = (const float*)d_in[1];
    const float* V = (const float*)d_in[2];
    float* out = (float*)d_out;

    fused_kernel<<<N_RED + N_BRD, 256>>>(Q, K, V, out);
}